// round 3
// baseline (speedup 1.0000x reference)
#include <cuda_runtime.h>
#include <cuda_bf16.h>
#include <cstdint>
#include <cstddef>

static constexpr int   N     = 4096;
static constexpr int   NB    = 32;            // 128-tiles per side
static constexpr int   SPLIT = 90;            // bf16 iterations before fp32 polish
static constexpr float CINV  = 1.0f / 1.000001f;

// ---------------------------------------------------------------------------
// Device scratch (allocation-free rule: __device__ globals)
// ---------------------------------------------------------------------------
static __device__ float         g_Js[(size_t)N * N];  // 64 MB symmetrized J (fp32)
static __device__ __nv_bfloat16 g_G [(size_t)N * N];  // 32 MB: Js(bf16) during iters, then G
static __device__ __nv_bfloat16 g_H [(size_t)N * N];  // 32 MB: H = G + G^2
static __device__ float         g_m [2][N];
static __device__ float         g_d [N];
static __device__ float         g_w [N];

// ---------------------------------------------------------------------------
// bf16 MMA wrapper (baseline PTX, sm_80+; no tcgen05 — compute_103 safe)
// ---------------------------------------------------------------------------
__device__ __forceinline__ void mma_bf16(float* c, const uint32_t* a, const uint32_t* b) {
    asm volatile(
        "mma.sync.aligned.m16n8k16.row.col.f32.bf16.bf16.f32 "
        "{%0,%1,%2,%3}, {%4,%5,%6,%7}, {%8,%9}, {%0,%1,%2,%3};\n"
        : "+f"(c[0]), "+f"(c[1]), "+f"(c[2]), "+f"(c[3])
        : "r"(a[0]), "r"(a[1]), "r"(a[2]), "r"(a[3]), "r"(b[0]), "r"(b[1]));
}

// ---------------------------------------------------------------------------
// k_zero: clear whole output
// ---------------------------------------------------------------------------
__global__ void k_zero(float* out, long long n) {
    long long i = (long long)blockIdx.x * blockDim.x + threadIdx.x;
    long long stride = (long long)gridDim.x * blockDim.x;
    for (; i < n; i += stride) out[i] = 0.0f;
}

// ---------------------------------------------------------------------------
// k_prep: Js = sym(J) with zero diag (fp32) + bf16 copy into g_G
// ---------------------------------------------------------------------------
__global__ void k_prep(const float* __restrict__ J) {
    __shared__ float ta[32][33];
    __shared__ float tb[32][33];
    int bi = blockIdx.y * 32, bj = blockIdx.x * 32;
    int r = threadIdx.y, c = threadIdx.x;
    ta[r][c] = J[(size_t)(bi + r) * N + (bj + c)];
    tb[r][c] = J[(size_t)(bj + r) * N + (bi + c)];
    __syncthreads();
    int i = bi + r, j = bj + c;
    float v = (i == j) ? 0.0f : 0.5f * (ta[r][c] + tb[c][r]);
    size_t idx = (size_t)i * N + j;
    g_Js[idx] = v;
    g_G[idx]  = __float2bfloat16(v);
}

// ---------------------------------------------------------------------------
// m0 = tanh(h)
// ---------------------------------------------------------------------------
__global__ void k_minit(const float* __restrict__ h) {
    int i = blockIdx.x * blockDim.x + threadIdx.x;
    if (i < N) g_m[0][i] = tanhf(h[i]);
}

// ---------------------------------------------------------------------------
// Fused iteration kernels (warp per row): s1 = Js@m, s2 = (Js*Js)@(m(1-m))
// ---------------------------------------------------------------------------
__global__ void __launch_bounds__(256) k_iter_bf16(const float* __restrict__ h, int pin) {
    int lane = threadIdx.x & 31, w = threadIdx.x >> 5;
    int row = blockIdx.x * 8 + w;
    const float* mi_v = g_m[pin];
    float* mo_v = g_m[pin ^ 1];
    const uint4* Jr = (const uint4*)(g_G + (size_t)row * N);   // 8 bf16 per uint4
    const float4* mv = (const float4*)mi_v;
    float s1 = 0.f, s2 = 0.f;
#pragma unroll 4
    for (int q = lane; q < N / 8; q += 32) {
        uint4 v = Jr[q];
        const __nv_bfloat162* b2 = reinterpret_cast<const __nv_bfloat162*>(&v);
        float4 m0 = mv[2 * q], m1 = mv[2 * q + 1];
        float2 a0 = __bfloat1622float2(b2[0]);
        float2 a1 = __bfloat1622float2(b2[1]);
        float2 a2 = __bfloat1622float2(b2[2]);
        float2 a3 = __bfloat1622float2(b2[3]);
        s1 = fmaf(a0.x, m0.x, s1); s1 = fmaf(a0.y, m0.y, s1);
        s1 = fmaf(a1.x, m0.z, s1); s1 = fmaf(a1.y, m0.w, s1);
        s1 = fmaf(a2.x, m1.x, s1); s1 = fmaf(a2.y, m1.y, s1);
        s1 = fmaf(a3.x, m1.z, s1); s1 = fmaf(a3.y, m1.w, s1);
        s2 = fmaf(a0.x * a0.x, m0.x * (1.f - m0.x), s2);
        s2 = fmaf(a0.y * a0.y, m0.y * (1.f - m0.y), s2);
        s2 = fmaf(a1.x * a1.x, m0.z * (1.f - m0.z), s2);
        s2 = fmaf(a1.y * a1.y, m0.w * (1.f - m0.w), s2);
        s2 = fmaf(a2.x * a2.x, m1.x * (1.f - m1.x), s2);
        s2 = fmaf(a2.y * a2.y, m1.y * (1.f - m1.y), s2);
        s2 = fmaf(a3.x * a3.x, m1.z * (1.f - m1.z), s2);
        s2 = fmaf(a3.y * a3.y, m1.w * (1.f - m1.w), s2);
    }
#pragma unroll
    for (int o = 16; o; o >>= 1) {
        s1 += __shfl_xor_sync(0xFFFFFFFFu, s1, o);
        s2 += __shfl_xor_sync(0xFFFFFFFFu, s2, o);
    }
    if (lane == 0) {
        float mi = mi_v[row];
        mo_v[row] = 0.5f * (mi + tanhf(h[row] + s1 - mi * s2));
    }
}

__global__ void __launch_bounds__(256) k_iter_f32(const float* __restrict__ h, int pin) {
    int lane = threadIdx.x & 31, w = threadIdx.x >> 5;
    int row = blockIdx.x * 8 + w;
    const float* mi_v = g_m[pin];
    float* mo_v = g_m[pin ^ 1];
    const float4* Jr = (const float4*)(g_Js + (size_t)row * N);
    const float4* mv = (const float4*)mi_v;
    float s1 = 0.f, s2 = 0.f;
#pragma unroll 4
    for (int q = lane; q < N / 4; q += 32) {
        float4 a = Jr[q];
        float4 b = mv[q];
        s1 = fmaf(a.x, b.x, s1); s1 = fmaf(a.y, b.y, s1);
        s1 = fmaf(a.z, b.z, s1); s1 = fmaf(a.w, b.w, s1);
        s2 = fmaf(a.x * a.x, b.x * (1.f - b.x), s2);
        s2 = fmaf(a.y * a.y, b.y * (1.f - b.y), s2);
        s2 = fmaf(a.z * a.z, b.z * (1.f - b.z), s2);
        s2 = fmaf(a.w * a.w, b.w * (1.f - b.w), s2);
    }
#pragma unroll
    for (int o = 16; o; o >>= 1) {
        s1 += __shfl_xor_sync(0xFFFFFFFFu, s1, o);
        s2 += __shfl_xor_sync(0xFFFFFFFFu, s2, o);
    }
    if (lane == 0) {
        float mi = mi_v[row];
        mo_v[row] = 0.5f * (mi + tanhf(h[row] + s1 - mi * s2));
    }
}

// ---------------------------------------------------------------------------
// k_vec: finalize m (in g_m[0] after 100 iters), compute d, w, write m to out
// ---------------------------------------------------------------------------
__global__ void k_vec(float* out, int writeM) {
    int i = blockIdx.x * blockDim.x + threadIdx.x;
    if (i < N) {
        float m = g_m[0][i];
        float d = 1.0f - m * m;
        g_d[i] = d;
        g_w[i] = sqrtf(d);
        if (writeM) out[i] = m;
    }
}

// ---------------------------------------------------------------------------
// k_buildG: G_ij = CINV * w_i * Js_ij * w_j (bf16), overwrites g_G
// ---------------------------------------------------------------------------
__global__ void k_buildG() {
    size_t q = (size_t)blockIdx.x * blockDim.x + threadIdx.x;  // float4 index
    size_t nq = (size_t)N * N / 4;
    if (q >= nq) return;
    size_t base = q * 4;
    int i = (int)(base >> 12);
    int j = (int)(base & (N - 1));
    float4 a = *(const float4*)(g_Js + base);
    float s = CINV * g_w[i];
    float2 r0, r1;
    r0.x = s * g_w[j + 0] * a.x;  r0.y = s * g_w[j + 1] * a.y;
    r1.x = s * g_w[j + 2] * a.z;  r1.y = s * g_w[j + 3] * a.w;
    __nv_bfloat162* dst = reinterpret_cast<__nv_bfloat162*>(g_G + base);
    dst[0] = __float22bfloat162_rn(r0);
    dst[1] = __float22bfloat162_rn(r1);
}

// ---------------------------------------------------------------------------
// k_gemm: 128x128 upper-triangle tile (bi<=bj), bf16 mma.sync, K=4096.
//   pass 1: D = G*G^T       -> H = G + D (bf16)
//   pass 2: D = G*H^T (=S)  -> cov epilogue into out (strictly upper)
// Both operand tiles stored [row][k] in smem (k-contiguous), LDT=40 pad.
// ---------------------------------------------------------------------------
static constexpr int KC  = 32;     // k-chunk
static constexpr int LDT = 40;     // smem row stride (bf16 elems)

__global__ void __launch_bounds__(256) k_gemm(int pass, float* out, long long covBase) {
    __shared__ __nv_bfloat16 sA[2][128 * LDT];
    __shared__ __nv_bfloat16 sB[2][128 * LDT];

    // decode linear block id -> upper-triangle tile (bi, bj)
    int rem = blockIdx.x;
    int bi = 0;
    while (rem >= NB - bi) { rem -= NB - bi; bi++; }
    int bj = bi + rem;
    int i0 = bi * 128, j0 = bj * 128;

    const __nv_bfloat16* Aop = g_G;
    const __nv_bfloat16* Bop = (pass == 1) ? g_G : g_H;

    int tid = threadIdx.x, lane = tid & 31, wid = tid >> 5;
    int wr = wid >> 2, wc = wid & 3;          // warp row (0..1), warp col (0..3)
    int gID = lane >> 2, tig = lane & 3;

    float acc[4][4][4];
#pragma unroll
    for (int a = 0; a < 4; a++)
#pragma unroll
        for (int b = 0; b < 4; b++)
#pragma unroll
            for (int c = 0; c < 4; c++) acc[a][b][c] = 0.f;

    // per-thread gmem slots: q = tid + t*256; r = q>>2 (row), g = q&3 (8-elem k group)
    uint4 ra[2], rb[2];
    int r_[2], g_[2];
#pragma unroll
    for (int t = 0; t < 2; t++) { int q = tid + t * 256; r_[t] = q >> 2; g_[t] = q & 3; }

    // prologue: load + store chunk 0
#pragma unroll
    for (int t = 0; t < 2; t++) {
        ra[t] = *(const uint4*)(Aop + (size_t)(i0 + r_[t]) * N + g_[t] * 8);
        rb[t] = *(const uint4*)(Bop + (size_t)(j0 + r_[t]) * N + g_[t] * 8);
    }
#pragma unroll
    for (int t = 0; t < 2; t++) {
        *(uint4*)&sA[0][r_[t] * LDT + g_[t] * 8] = ra[t];
        *(uint4*)&sB[0][r_[t] * LDT + g_[t] * 8] = rb[t];
    }
    __syncthreads();

    const int NCH = N / KC;   // 128
    for (int c = 0; c < NCH; c++) {
        int buf = c & 1;
        if (c + 1 < NCH) {
            int kc = (c + 1) * KC;
#pragma unroll
            for (int t = 0; t < 2; t++) {
                ra[t] = *(const uint4*)(Aop + (size_t)(i0 + r_[t]) * N + kc + g_[t] * 8);
                rb[t] = *(const uint4*)(Bop + (size_t)(j0 + r_[t]) * N + kc + g_[t] * 8);
            }
        }
#pragma unroll
        for (int kk = 0; kk < KC; kk += 16) {
            uint32_t af[4][4], bf[4][2];
#pragma unroll
            for (int mi = 0; mi < 4; mi++) {
                const __nv_bfloat16* base = &sA[buf][(wr * 64 + mi * 16 + gID) * LDT + kk + tig * 2];
                af[mi][0] = *(const uint32_t*)(base);
                af[mi][1] = *(const uint32_t*)(base + 8 * LDT);
                af[mi][2] = *(const uint32_t*)(base + 8);
                af[mi][3] = *(const uint32_t*)(base + 8 * LDT + 8);
            }
#pragma unroll
            for (int ni = 0; ni < 4; ni++) {
                const __nv_bfloat16* base = &sB[buf][(wc * 32 + ni * 8 + gID) * LDT + kk + tig * 2];
                bf[ni][0] = *(const uint32_t*)(base);
                bf[ni][1] = *(const uint32_t*)(base + 8);
            }
#pragma unroll
            for (int mi = 0; mi < 4; mi++)
#pragma unroll
                for (int ni = 0; ni < 4; ni++)
                    mma_bf16(acc[mi][ni], af[mi], bf[ni]);
        }
        __syncthreads();
        if (c + 1 < NCH) {
            int nb = (c + 1) & 1;
#pragma unroll
            for (int t = 0; t < 2; t++) {
                *(uint4*)&sA[nb][r_[t] * LDT + g_[t] * 8] = ra[t];
                *(uint4*)&sB[nb][r_[t] * LDT + g_[t] * 8] = rb[t];
            }
            __syncthreads();
        }
    }

    // epilogue
#pragma unroll
    for (int mi = 0; mi < 4; mi++) {
#pragma unroll
        for (int r8 = 0; r8 < 2; r8++) {
            int row = i0 + wr * 64 + mi * 16 + gID + r8 * 8;
            if (pass == 1) {
                __nv_bfloat16* dst = g_H + (size_t)row * N;
                const __nv_bfloat16* gsrc = g_G + (size_t)row * N;
#pragma unroll
                for (int ni = 0; ni < 4; ni++) {
                    int col = j0 + wc * 32 + ni * 8 + tig * 2;
                    float2 v;
                    v.x = acc[mi][ni][r8 * 2 + 0] + __bfloat162float(gsrc[col]);
                    v.y = acc[mi][ni][r8 * 2 + 1] + __bfloat162float(gsrc[col + 1]);
                    *(__nv_bfloat162*)(dst + col) = __float22bfloat162_rn(v);
                }
            } else {
                const float* jsrc = g_Js + (size_t)row * N;
                float mrow = g_m[0][row];
                float inv_wr = 1.0f / g_w[row];
#pragma unroll
                for (int ni = 0; ni < 4; ni++) {
                    int col = j0 + wc * 32 + ni * 8 + tig * 2;
#pragma unroll
                    for (int e = 0; e < 2; e++) {
                        int gj = col + e;
                        if (gj > row) {
                            float S = acc[mi][ni][r8 * 2 + e];
                            float cov = mrow * g_m[0][gj]
                                      + CINV * (CINV * jsrc[gj] * g_d[gj] + S * g_w[gj] * inv_wr);
                            out[covBase + (size_t)row * N + gj] = cov;
                        }
                    }
                }
            }
        }
    }
}

// ---------------------------------------------------------------------------
// k_mirrorH: H[r][c] = H[c][r] for r > c (coalesced 32x32 smem transpose)
// ---------------------------------------------------------------------------
__global__ void k_mirrorH() {
    int bx = blockIdx.x, by = blockIdx.y;       // source row tile, source col tile
    if (by < bx) return;
    __shared__ __nv_bfloat16 t[32][33];
    int tx = threadIdx.x, ty = threadIdx.y;
    t[ty][tx] = g_H[(size_t)(bx * 32 + ty) * N + (by * 32 + tx)];
    __syncthreads();
    int dr = by * 32 + ty, dc = bx * 32 + tx;
    if (dr > dc) g_H[(size_t)dr * N + dc] = t[tx][ty];
}

// ---------------------------------------------------------------------------
// kernel_launch
// ---------------------------------------------------------------------------
extern "C" void kernel_launch(void* const* d_in, const int* in_sizes, int n_in,
                              void* d_out, int out_size) {
    const float* h = nullptr;
    const float* J = nullptr;
    for (int i = 0; i < n_in; i++) {
        if (in_sizes[i] == N * N)   J = (const float*)d_in[i];
        else if (in_sizes[i] == N)  h = (const float*)d_in[i];
    }
    float* out = (float*)d_out;
    long long covBase = ((long long)out_size >= (long long)N * N + N) ? N : 0;

    k_zero<<<8192, 256>>>(out, (long long)out_size);
    k_prep<<<dim3(N / 32, N / 32), dim3(32, 32)>>>(J);
    k_minit<<<16, 256>>>(h);
    for (int t = 0; t < 100; t++) {
        if (t < SPLIT) k_iter_bf16<<<N / 8, 256>>>(h, t & 1);
        else           k_iter_f32 <<<N / 8, 256>>>(h, t & 1);
    }
    k_vec<<<16, 256>>>(out, covBase > 0 ? 1 : 0);
    k_buildG<<<(int)(((size_t)N * N / 4 + 255) / 256), 256>>>();
    k_gemm<<<NB * (NB + 1) / 2, 256>>>(1, out, covBase);
    k_mirrorH<<<dim3(N / 32, N / 32), dim3(32, 32)>>>();
    k_gemm<<<NB * (NB + 1) / 2, 256>>>(2, out, covBase);
}